// round 12
// baseline (speedup 1.0000x reference)
#include <cuda_runtime.h>
#include <cuda_fp16.h>
#include <cstdint>

#define DD 4096
#define BB 8192
#define OO 4096

// ---------------- scratch (device globals; no runtime alloc allowed) -------
static __device__ __half g_z[(size_t)BB * DD];   // 64 MB
static __device__ __half g_w[(size_t)OO * DD];   // 32 MB, holds W*U1
static __device__ float  g_c[BB];

// ---------------- helpers ---------------------------------------------------
__device__ __forceinline__ uint32_t smem_u32(const void* p) {
    uint32_t a;
    asm("{ .reg .u64 t; cvta.to.shared.u64 t, %1; cvt.u32.u64 %0, t; }" : "=r"(a) : "l"(p));
    return a;
}

__device__ __forceinline__ void cp_async16(uint32_t dst, const void* src) {
    asm volatile("cp.async.cg.shared.global [%0], [%1], 16;" :: "r"(dst), "l"(src));
}
__device__ __forceinline__ void cp_commit() {
    asm volatile("cp.async.commit_group;" ::: "memory");
}
template <int N>
__device__ __forceinline__ void cp_wait() {
    asm volatile("cp.async.wait_group %0;" :: "n"(N) : "memory");
}

__device__ __forceinline__ void ldsm_x4(uint32_t a[4], uint32_t addr) {
    asm volatile("ldmatrix.sync.aligned.m8n8.x4.shared.b16 {%0,%1,%2,%3}, [%4];"
                 : "=r"(a[0]), "=r"(a[1]), "=r"(a[2]), "=r"(a[3]) : "r"(addr));
}

// fp16-accumulate MMA, D/C chained in-place
__device__ __forceinline__ void mma16816_f16(uint32_t& d0, uint32_t& d1,
                                             const uint32_t a[4], const uint32_t b[2]) {
    asm volatile(
        "mma.sync.aligned.m16n8k16.row.col.f16.f16.f16.f16 "
        "{%0,%1}, {%2,%3,%4,%5}, {%6,%7}, {%0,%1};"
        : "+r"(d0), "+r"(d1)
        : "r"(a[0]), "r"(a[1]), "r"(a[2]), "r"(a[3]), "r"(b[0]), "r"(b[1]));
}

// ---------------- fused prep kernel -----------------------------------------
__global__ void __launch_bounds__(256) prep_kernel(const float* __restrict__ z,
                                                   const float* __restrict__ U1,
                                                   const float* __restrict__ U2,
                                                   const float* __restrict__ U3,
                                                   const float* __restrict__ W) {
    int t = threadIdx.x;
    if (blockIdx.x < BB) {
        int b = blockIdx.x;
        const float4* zr  = (const float4*)z + (size_t)b * (DD / 4);
        const float4* u2p = (const float4*)U2;
        const float4* u3p = (const float4*)U3;
        uint2* zo = (uint2*)(g_z + (size_t)b * DD);

        float s2 = 0.f, s3 = 0.f;
#pragma unroll
        for (int j = 0; j < 4; j++) {
            int i = j * 256 + t;
            float4 zv = zr[i];
            float4 a2 = u2p[i];
            float4 a3 = u3p[i];
            s2 += zv.x * a2.x + zv.y * a2.y + zv.z * a2.z + zv.w * a2.w;
            s3 += zv.x * a3.x + zv.y * a3.y + zv.z * a3.z + zv.w * a3.w;
            __half2 h0 = __floats2half2_rn(zv.x, zv.y);
            __half2 h1 = __floats2half2_rn(zv.z, zv.w);
            uint2 pv;
            pv.x = *(uint32_t*)&h0;
            pv.y = *(uint32_t*)&h1;
            zo[i] = pv;
        }
#pragma unroll
        for (int o = 16; o > 0; o >>= 1) {
            s2 += __shfl_xor_sync(0xFFFFFFFFu, s2, o);
            s3 += __shfl_xor_sync(0xFFFFFFFFu, s3, o);
        }
        __shared__ float r2[8], r3[8];
        int wid = t >> 5, lid = t & 31;
        if (lid == 0) { r2[wid] = s2; r3[wid] = s3; }
        __syncthreads();
        if (t == 0) {
            float a = 0.f, c = 0.f;
#pragma unroll
            for (int i = 0; i < 8; i++) { a += r2[i]; c += r3[i]; }
            g_c[b] = a * c;
        }
    } else {
        const float4* w4 = (const float4*)W;
        const float4* u4 = (const float4*)U1;
        uint2* wo = (uint2*)g_w;
        size_t total = (size_t)OO * (DD / 4);
        size_t stride = (size_t)2048 * 256;
        for (size_t f = (size_t)(blockIdx.x - BB) * 256 + t; f < total; f += stride) {
            float4 w = w4[f];
            float4 u = u4[f & (DD / 4 - 1)];
            __half2 h0 = __floats2half2_rn(w.x * u.x, w.y * u.y);
            __half2 h1 = __floats2half2_rn(w.z * u.z, w.w * u.w);
            uint2 pv;
            pv.x = *(uint32_t*)&h0;
            pv.y = *(uint32_t*)&h1;
            wo[f] = pv;
        }
    }
}

// ---------------- GEMM: out[b,o] = c[b]*sum_k z16[b,k]*w16[o,k] + bias[o] ---
// CTA tile 128(M) x 256(N), K-chunk 64, 512 threads (16 warps, warp 64x32).
// Anti-serialization round:
//  - Rolling A-fragment prefetch: af[mi+1] loaded BEFORE MMAs of mi, so the
//    LDSM->MMA dependency is off the critical path.
//  - Warp phase-stagger: warp-group (wid>>2), distinct per warp within each
//    SMSP, starts the ks phase loop at a rotated position, de-correlating
//    crossbar bursts from MMA bursts across co-resident warps.
// f16 MMAs chained through C across the 4 k-steps of one iter, promoted to
// fp32 once per iter (numerics identical to R7/R11: rel_err ~4.4e-4).
#define TM 128
#define TN 256
#define KITERS (DD / 64)                // 64
#define STAGES 3
#define PITCH 144u
#define STG_A (TM * PITCH)              // 18432
#define STG_B (TN * PITCH)              // 36864
#define STG_BYTES (STG_A + STG_B)       // 55296
#define GEMM_SMEM (STAGES * STG_BYTES)  // 165888

__global__ void __launch_bounds__(512, 1) gemm_kernel(const float* __restrict__ bias,
                                                      float* __restrict__ out) {
    extern __shared__ char smem[];
    uint32_t sb = smem_u32(smem);
    int tid = threadIdx.x;
    int wid = tid >> 5, lane = tid & 31;
    int m0 = blockIdx.y * TM;
    int n0 = blockIdx.x * TN;
    int wm = wid & 1;        // 2 M warp-tiles of 64
    int wn = wid >> 1;       // 8 N warp-tiles of 32
    int wstag = wid >> 2;    // 0..3, distinct per warp within an SMSP (SMSP = wid&3)

    float acc[4][4][4];
#pragma unroll
    for (int i = 0; i < 4; i++)
#pragma unroll
        for (int j = 0; j < 4; j++)
#pragma unroll
            for (int q = 0; q < 4; q++) acc[i][j][q] = 0.f;

    const __half* zb = g_z + (size_t)m0 * DD;
    const __half* wb = g_w + (size_t)n0 * DD;

    auto load_stage = [&](int it) {
        int s = it - (it / STAGES) * STAGES;
        uint32_t base = sb + (uint32_t)s * STG_BYTES;
        int kb = it * 64;
#pragma unroll
        for (int j = 0; j < 2; j++) {
            int c = tid + (j << 9);
            int r = c >> 3, ch = c & 7;
            cp_async16(base + (uint32_t)r * PITCH + (uint32_t)(ch << 4),
                       zb + (size_t)r * DD + kb + (ch << 3));
        }
#pragma unroll
        for (int j = 0; j < 4; j++) {
            int c = tid + (j << 9);
            int r = c >> 3, ch = c & 7;
            cp_async16(base + STG_A + (uint32_t)r * PITCH + (uint32_t)(ch << 4),
                       wb + (size_t)r * DD + kb + (ch << 3));
        }
        cp_commit();
    };

#pragma unroll
    for (int p = 0; p < STAGES - 1; p++) load_stage(p);

    // intra-warp ldmatrix offsets
    uint32_t a_row = (uint32_t)(wm * 64 + (lane & 15));
    uint32_t a_kof = (uint32_t)((lane >> 4) << 3) * 2u;
    uint32_t b_row = (uint32_t)(wn * 32 + ((lane >> 4) << 3) + (lane & 7));
    uint32_t b_kof = (uint32_t)(((lane >> 3) & 1) << 3) * 2u;

    for (int it = 0; it < KITERS; ++it) {
        if (it < KITERS - 1) cp_wait<1>();
        else                 cp_wait<0>();
        __syncthreads();

        if (it + STAGES - 1 < KITERS) load_stage(it + STAGES - 1);

        int s = it - (it / STAGES) * STAGES;
        uint32_t aS = sb + (uint32_t)s * STG_BYTES;
        uint32_t bS = aS + STG_A;

        // f16 chain accumulators for this iter (4 chained K16 MMAs per tile)
        uint32_t dch[4][4][2];
#pragma unroll
        for (int i = 0; i < 4; i++)
#pragma unroll
            for (int j = 0; j < 4; j++) { dch[i][j][0] = 0u; dch[i][j][1] = 0u; }

        // rolling A-fragment prefetch across the 4 staggered phases
        uint32_t af_cur[4], af_next[4];
        {
            uint32_t k0 = (uint32_t)((wstag & 3) * 32);
            ldsm_x4(af_cur, aS + a_row * PITCH + k0 + a_kof);
        }
#pragma unroll
        for (int ks = 0; ks < 4; ks++) {
            uint32_t koff   = (uint32_t)(((ks + wstag) & 3) * 32);
            uint32_t koff_n = (uint32_t)(((ks + 1 + wstag) & 3) * 32);
            uint32_t bf[2][4];
            ldsm_x4(bf[0], bS + b_row * PITCH + koff + b_kof);
            ldsm_x4(bf[1], bS + (b_row + 16u) * PITCH + koff + b_kof);
#pragma unroll
            for (int mi = 0; mi < 4; mi++) {
                // prefetch the next A fragment before issuing this tile's MMAs
                if (mi < 3)
                    ldsm_x4(af_next, aS + (a_row + (uint32_t)((mi + 1) * 16)) * PITCH +
                                         koff + a_kof);
                else if (ks < 3)
                    ldsm_x4(af_next, aS + a_row * PITCH + koff_n + a_kof);
#pragma unroll
                for (int nj = 0; nj < 4; nj++)
                    mma16816_f16(dch[mi][nj][0], dch[mi][nj][1],
                                 af_cur, &bf[nj >> 1][(nj & 1) * 2]);
#pragma unroll
                for (int q = 0; q < 4; q++) af_cur[q] = af_next[q];
            }
        }

        // promote once per iter
#pragma unroll
        for (int mi = 0; mi < 4; mi++)
#pragma unroll
            for (int nj = 0; nj < 4; nj++) {
                float2 f0 = __half22float2(*(__half2*)&dch[mi][nj][0]);
                float2 f1 = __half22float2(*(__half2*)&dch[mi][nj][1]);
                acc[mi][nj][0] += f0.x;
                acc[mi][nj][1] += f0.y;
                acc[mi][nj][2] += f1.x;
                acc[mi][nj][3] += f1.y;
            }
    }
    __syncthreads();

    // epilogue: out = c[m]*acc + bias[n]
    int col_base = n0 + wn * 32 + (lane & 3) * 2;
    float bb[4][2];
#pragma unroll
    for (int nj = 0; nj < 4; nj++) {
        bb[nj][0] = __ldg(bias + col_base + nj * 8);
        bb[nj][1] = __ldg(bias + col_base + nj * 8 + 1);
    }
#pragma unroll
    for (int mi = 0; mi < 4; mi++) {
        int r0 = m0 + wm * 64 + mi * 16 + (lane >> 2);
        float c0 = __ldg(g_c + r0);
        float c1 = __ldg(g_c + r0 + 8);
        float* o0 = out + (size_t)r0 * OO;
        float* o1 = o0 + (size_t)8 * OO;
#pragma unroll
        for (int nj = 0; nj < 4; nj++) {
            int col = col_base + nj * 8;
            float2 v0, v1;
            v0.x = c0 * acc[mi][nj][0] + bb[nj][0];
            v0.y = c0 * acc[mi][nj][1] + bb[nj][1];
            v1.x = c1 * acc[mi][nj][2] + bb[nj][0];
            v1.y = c1 * acc[mi][nj][3] + bb[nj][1];
            *(float2*)(o0 + col) = v0;
            *(float2*)(o1 + col) = v1;
        }
    }
}

// ---------------- launch ----------------------------------------------------
extern "C" void kernel_launch(void* const* d_in, const int* in_sizes, int n_in,
                              void* d_out, int out_size) {
    (void)in_sizes; (void)n_in; (void)out_size;
    const float* z    = (const float*)d_in[0];
    const float* U1   = (const float*)d_in[1];
    const float* U2   = (const float*)d_in[2];
    const float* U3   = (const float*)d_in[3];
    const float* W    = (const float*)d_in[4];
    const float* bias = (const float*)d_in[5];
    float* out = (float*)d_out;

    prep_kernel<<<BB + 2048, 256>>>(z, U1, U2, U3, W);

    static bool attr_set = false;
    if (!attr_set) {
        cudaFuncSetAttribute(gemm_kernel, cudaFuncAttributeMaxDynamicSharedMemorySize,
                             GEMM_SMEM);
        attr_set = true;
    }
    dim3 grid(OO / TN, BB / TM);
    gemm_kernel<<<grid, 512, GEMM_SMEM>>>(bias, out);
}

// round 13
// speedup vs baseline: 1.1727x; 1.1727x over previous
#include <cuda_runtime.h>
#include <cuda_fp16.h>
#include <cstdint>

#define DD 4096
#define BB 8192
#define OO 4096

// ---------------- scratch (device globals; no runtime alloc allowed) -------
static __device__ __half g_z[(size_t)BB * DD];   // 64 MB
static __device__ __half g_w[(size_t)OO * DD];   // 32 MB, holds W*U1
static __device__ float  g_c[BB];

// ---------------- helpers ---------------------------------------------------
__device__ __forceinline__ uint32_t smem_u32(const void* p) {
    uint32_t a;
    asm("{ .reg .u64 t; cvta.to.shared.u64 t, %1; cvt.u32.u64 %0, t; }" : "=r"(a) : "l"(p));
    return a;
}

__device__ __forceinline__ void cp_async16(uint32_t dst, const void* src) {
    asm volatile("cp.async.cg.shared.global [%0], [%1], 16;" :: "r"(dst), "l"(src));
}
__device__ __forceinline__ void cp_commit() {
    asm volatile("cp.async.commit_group;" ::: "memory");
}
template <int N>
__device__ __forceinline__ void cp_wait() {
    asm volatile("cp.async.wait_group %0;" :: "n"(N) : "memory");
}

__device__ __forceinline__ void ldsm_x4(uint32_t a[4], uint32_t addr) {
    asm volatile("ldmatrix.sync.aligned.m8n8.x4.shared.b16 {%0,%1,%2,%3}, [%4];"
                 : "=r"(a[0]), "=r"(a[1]), "=r"(a[2]), "=r"(a[3]) : "r"(addr));
}

// fp16-accumulate MMA, D/C chained in-place
__device__ __forceinline__ void mma16816_f16(uint32_t& d0, uint32_t& d1,
                                             const uint32_t a[4], const uint32_t b[2]) {
    asm volatile(
        "mma.sync.aligned.m16n8k16.row.col.f16.f16.f16.f16 "
        "{%0,%1}, {%2,%3,%4,%5}, {%6,%7}, {%0,%1};"
        : "+r"(d0), "+r"(d1)
        : "r"(a[0]), "r"(a[1]), "r"(a[2]), "r"(a[3]), "r"(b[0]), "r"(b[1]));
}

// ---------------- fused prep kernel -----------------------------------------
__global__ void __launch_bounds__(256) prep_kernel(const float* __restrict__ z,
                                                   const float* __restrict__ U1,
                                                   const float* __restrict__ U2,
                                                   const float* __restrict__ U3,
                                                   const float* __restrict__ W) {
    int t = threadIdx.x;
    if (blockIdx.x < BB) {
        int b = blockIdx.x;
        const float4* zr  = (const float4*)z + (size_t)b * (DD / 4);
        const float4* u2p = (const float4*)U2;
        const float4* u3p = (const float4*)U3;
        uint2* zo = (uint2*)(g_z + (size_t)b * DD);

        float s2 = 0.f, s3 = 0.f;
#pragma unroll
        for (int j = 0; j < 4; j++) {
            int i = j * 256 + t;
            float4 zv = zr[i];
            float4 a2 = u2p[i];
            float4 a3 = u3p[i];
            s2 += zv.x * a2.x + zv.y * a2.y + zv.z * a2.z + zv.w * a2.w;
            s3 += zv.x * a3.x + zv.y * a3.y + zv.z * a3.z + zv.w * a3.w;
            __half2 h0 = __floats2half2_rn(zv.x, zv.y);
            __half2 h1 = __floats2half2_rn(zv.z, zv.w);
            uint2 pv;
            pv.x = *(uint32_t*)&h0;
            pv.y = *(uint32_t*)&h1;
            zo[i] = pv;
        }
#pragma unroll
        for (int o = 16; o > 0; o >>= 1) {
            s2 += __shfl_xor_sync(0xFFFFFFFFu, s2, o);
            s3 += __shfl_xor_sync(0xFFFFFFFFu, s3, o);
        }
        __shared__ float r2[8], r3[8];
        int wid = t >> 5, lid = t & 31;
        if (lid == 0) { r2[wid] = s2; r3[wid] = s3; }
        __syncthreads();
        if (t == 0) {
            float a = 0.f, c = 0.f;
#pragma unroll
            for (int i = 0; i < 8; i++) { a += r2[i]; c += r3[i]; }
            g_c[b] = a * c;
        }
    } else {
        const float4* w4 = (const float4*)W;
        const float4* u4 = (const float4*)U1;
        uint2* wo = (uint2*)g_w;
        size_t total = (size_t)OO * (DD / 4);
        size_t stride = (size_t)2048 * 256;
        for (size_t f = (size_t)(blockIdx.x - BB) * 256 + t; f < total; f += stride) {
            float4 w = w4[f];
            float4 u = u4[f & (DD / 4 - 1)];
            __half2 h0 = __floats2half2_rn(w.x * u.x, w.y * u.y);
            __half2 h1 = __floats2half2_rn(w.z * u.z, w.w * u.w);
            uint2 pv;
            pv.x = *(uint32_t*)&h0;
            pv.y = *(uint32_t*)&h1;
            wo[f] = pv;
        }
    }
}

// ---------------- GEMM: out[b,o] = c[b]*sum_k z16[b,k]*w16[o,k] + bias[o] ---
// CTA tile 128(M) x 256(N), K-chunk 64, 256 threads (8 warps), WARP TILE 64x64.
// Crossbar-traffic round: warp 64x64 halves both A (x8->x4) and B (x2... TM/WM
// stays 2) duplication vs 64x32: LDSM 192KB -> 128KB per iter. 8 warps = 128
// threads/SMSP -> 255 regs/thread available (acc 128 fp32 + dch 64 + frags).
// f16 MMAs chained through C across the 4 k-steps of one iter, promoted to
// fp32 once per iter (numerics identical: rel_err ~4.4e-4).
#define TM 128
#define TN 256
#define KITERS (DD / 64)                // 64
#define STAGES 3
#define PITCH 144u
#define STG_A (TM * PITCH)              // 18432
#define STG_B (TN * PITCH)              // 36864
#define STG_BYTES (STG_A + STG_B)       // 55296
#define GEMM_SMEM (STAGES * STG_BYTES)  // 165888

__global__ void __launch_bounds__(256, 1) gemm_kernel(const float* __restrict__ bias,
                                                      float* __restrict__ out) {
    extern __shared__ char smem[];
    uint32_t sb = smem_u32(smem);
    int tid = threadIdx.x;
    int wid = tid >> 5, lane = tid & 31;
    int m0 = blockIdx.y * TM;
    int n0 = blockIdx.x * TN;
    int wm = wid & 1;        // 2 M warp-groups of 64
    int wn = wid >> 1;       // 4 N warp-groups of 64

    float acc[4][8][4];
#pragma unroll
    for (int i = 0; i < 4; i++)
#pragma unroll
        for (int j = 0; j < 8; j++)
#pragma unroll
            for (int q = 0; q < 4; q++) acc[i][j][q] = 0.f;

    const __half* zb = g_z + (size_t)m0 * DD;
    const __half* wb = g_w + (size_t)n0 * DD;

    // per stage: A 1024 chunks + B 2048 chunks of 16B over 256 threads -> 12 each
    auto load_stage = [&](int it) {
        int s = it - (it / STAGES) * STAGES;
        uint32_t base = sb + (uint32_t)s * STG_BYTES;
        int kb = it * 64;
#pragma unroll
        for (int j = 0; j < 4; j++) {
            int c = tid + (j << 8);
            int r = c >> 3, ch = c & 7;
            cp_async16(base + (uint32_t)r * PITCH + (uint32_t)(ch << 4),
                       zb + (size_t)r * DD + kb + (ch << 3));
        }
#pragma unroll
        for (int j = 0; j < 8; j++) {
            int c = tid + (j << 8);
            int r = c >> 3, ch = c & 7;
            cp_async16(base + STG_A + (uint32_t)r * PITCH + (uint32_t)(ch << 4),
                       wb + (size_t)r * DD + kb + (ch << 3));
        }
        cp_commit();
    };

#pragma unroll
    for (int p = 0; p < STAGES - 1; p++) load_stage(p);

    // intra-warp ldmatrix offsets
    uint32_t a_row = (uint32_t)(wm * 64 + (lane & 15));
    uint32_t a_kof = (uint32_t)((lane >> 4) << 3) * 2u;
    uint32_t b_row = (uint32_t)(wn * 64 + ((lane >> 4) << 3) + (lane & 7));
    uint32_t b_kof = (uint32_t)(((lane >> 3) & 1) << 3) * 2u;

    for (int it = 0; it < KITERS; ++it) {
        if (it < KITERS - 1) cp_wait<1>();
        else                 cp_wait<0>();
        __syncthreads();

        if (it + STAGES - 1 < KITERS) load_stage(it + STAGES - 1);

        int s = it - (it / STAGES) * STAGES;
        uint32_t aS = sb + (uint32_t)s * STG_BYTES;
        uint32_t bS = aS + STG_A;

        // f16 chain accumulators for this iter (4 chained K16 MMAs per tile)
        uint32_t dch[4][8][2];
#pragma unroll
        for (int i = 0; i < 4; i++)
#pragma unroll
            for (int j = 0; j < 8; j++) { dch[i][j][0] = 0u; dch[i][j][1] = 0u; }

        // 4 k-phases over the K64 chunk
#pragma unroll
        for (int ks = 0; ks < 4; ks++) {
            uint32_t koff = (uint32_t)(ks * 32);
            uint32_t bf[4][4];
#pragma unroll
            for (int pj = 0; pj < 4; pj++)
                ldsm_x4(bf[pj], bS + (b_row + (uint32_t)(pj * 16)) * PITCH + koff + b_kof);
#pragma unroll
            for (int mi = 0; mi < 4; mi++) {
                uint32_t af[4];
                ldsm_x4(af, aS + (a_row + (uint32_t)(mi * 16)) * PITCH + koff + a_kof);
#pragma unroll
                for (int nj = 0; nj < 8; nj++)
                    mma16816_f16(dch[mi][nj][0], dch[mi][nj][1],
                                 af, &bf[nj >> 1][(nj & 1) * 2]);
            }
        }

        // promote once per iter
#pragma unroll
        for (int mi = 0; mi < 4; mi++)
#pragma unroll
            for (int nj = 0; nj < 8; nj++) {
                float2 f0 = __half22float2(*(__half2*)&dch[mi][nj][0]);
                float2 f1 = __half22float2(*(__half2*)&dch[mi][nj][1]);
                acc[mi][nj][0] += f0.x;
                acc[mi][nj][1] += f0.y;
                acc[mi][nj][2] += f1.x;
                acc[mi][nj][3] += f1.y;
            }
    }
    __syncthreads();

    // epilogue: out = c[m]*acc + bias[n]
    int col_base = n0 + wn * 64 + (lane & 3) * 2;
    float bb[8][2];
#pragma unroll
    for (int nj = 0; nj < 8; nj++) {
        bb[nj][0] = __ldg(bias + col_base + nj * 8);
        bb[nj][1] = __ldg(bias + col_base + nj * 8 + 1);
    }
#pragma unroll
    for (int mi = 0; mi < 4; mi++) {
        int r0 = m0 + wm * 64 + mi * 16 + (lane >> 2);
        float c0 = __ldg(g_c + r0);
        float c1 = __ldg(g_c + r0 + 8);
        float* o0 = out + (size_t)r0 * OO;
        float* o1 = o0 + (size_t)8 * OO;
#pragma unroll
        for (int nj = 0; nj < 8; nj++) {
            int col = col_base + nj * 8;
            float2 v0, v1;
            v0.x = c0 * acc[mi][nj][0] + bb[nj][0];
            v0.y = c0 * acc[mi][nj][1] + bb[nj][1];
            v1.x = c1 * acc[mi][nj][2] + bb[nj][0];
            v1.y = c1 * acc[mi][nj][3] + bb[nj][1];
            *(float2*)(o0 + col) = v0;
            *(float2*)(o1 + col) = v1;
        }
    }
}

// ---------------- launch ----------------------------------------------------
extern "C" void kernel_launch(void* const* d_in, const int* in_sizes, int n_in,
                              void* d_out, int out_size) {
    (void)in_sizes; (void)n_in; (void)out_size;
    const float* z    = (const float*)d_in[0];
    const float* U1   = (const float*)d_in[1];
    const float* U2   = (const float*)d_in[2];
    const float* U3   = (const float*)d_in[3];
    const float* W    = (const float*)d_in[4];
    const float* bias = (const float*)d_in[5];
    float* out = (float*)d_out;

    prep_kernel<<<BB + 2048, 256>>>(z, U1, U2, U3, W);

    static bool attr_set = false;
    if (!attr_set) {
        cudaFuncSetAttribute(gemm_kernel, cudaFuncAttributeMaxDynamicSharedMemorySize,
                             GEMM_SMEM);
        attr_set = true;
    }
    dim3 grid(OO / TN, BB / TM);
    gemm_kernel<<<grid, 256, GEMM_SMEM>>>(bias, out);
}

// round 14
// speedup vs baseline: 1.2390x; 1.0565x over previous
#include <cuda_runtime.h>
#include <cuda_fp16.h>
#include <cstdint>

#define DD 4096
#define BB 8192
#define OO 4096

// ---------------- scratch (device globals; no runtime alloc allowed) -------
static __device__ __half g_z[(size_t)BB * DD];   // 64 MB
static __device__ __half g_w[(size_t)OO * DD];   // 32 MB, holds W*U1
static __device__ float  g_c[BB];

// ---------------- helpers ---------------------------------------------------
__device__ __forceinline__ uint32_t smem_u32(const void* p) {
    uint32_t a;
    asm("{ .reg .u64 t; cvta.to.shared.u64 t, %1; cvt.u32.u64 %0, t; }" : "=r"(a) : "l"(p));
    return a;
}

__device__ __forceinline__ void cp_async16(uint32_t dst, const void* src) {
    asm volatile("cp.async.cg.shared.global [%0], [%1], 16;" :: "r"(dst), "l"(src));
}
__device__ __forceinline__ void cp_commit() {
    asm volatile("cp.async.commit_group;" ::: "memory");
}
template <int N>
__device__ __forceinline__ void cp_wait() {
    asm volatile("cp.async.wait_group %0;" :: "n"(N) : "memory");
}

__device__ __forceinline__ void ldsm_x4(uint32_t a[4], uint32_t addr) {
    asm volatile("ldmatrix.sync.aligned.m8n8.x4.shared.b16 {%0,%1,%2,%3}, [%4];"
                 : "=r"(a[0]), "=r"(a[1]), "=r"(a[2]), "=r"(a[3]) : "r"(addr));
}

// fp16-accumulate MMA, D/C chained in-place
__device__ __forceinline__ void mma16816_f16(uint32_t& d0, uint32_t& d1,
                                             const uint32_t a[4], const uint32_t b[2]) {
    asm volatile(
        "mma.sync.aligned.m16n8k16.row.col.f16.f16.f16.f16 "
        "{%0,%1}, {%2,%3,%4,%5}, {%6,%7}, {%0,%1};"
        : "+r"(d0), "+r"(d1)
        : "r"(a[0]), "r"(a[1]), "r"(a[2]), "r"(a[3]), "r"(b[0]), "r"(b[1]));
}

// zero-C form: d = a*b + 0 (fresh accumulator, no explicit zeroing needed)
__device__ __forceinline__ void mma16816_f16_z(uint32_t& d0, uint32_t& d1,
                                               const uint32_t a[4], const uint32_t b[2]) {
    asm volatile(
        "mma.sync.aligned.m16n8k16.row.col.f16.f16.f16.f16 "
        "{%0,%1}, {%2,%3,%4,%5}, {%6,%7}, {%8,%9};"
        : "=r"(d0), "=r"(d1)
        : "r"(a[0]), "r"(a[1]), "r"(a[2]), "r"(a[3]), "r"(b[0]), "r"(b[1]),
          "r"(0u), "r"(0u));
}

__device__ __forceinline__ uint32_t pack_h2(float x, float y) {
    __half2 h = __floats2half2_rn(x, y);
    return *(uint32_t*)&h;
}

// ---------------- fused prep kernel -----------------------------------------
// blocks [0, BB): per-row scalar c[b] + z -> fp16 (16B stores)
// blocks [BB, BB+2048): W' = W*U1 -> fp16 (grid-stride, 16B stores)
__global__ void __launch_bounds__(256) prep_kernel(const float* __restrict__ z,
                                                   const float* __restrict__ U1,
                                                   const float* __restrict__ U2,
                                                   const float* __restrict__ U3,
                                                   const float* __restrict__ W) {
    int t = threadIdx.x;
    if (blockIdx.x < BB) {
        int b = blockIdx.x;
        const float4* zr  = (const float4*)z + (size_t)b * (DD / 4);
        const float4* u2p = (const float4*)U2;
        const float4* u3p = (const float4*)U3;
        uint4* zo = (uint4*)(g_z + (size_t)b * DD);

        float s2 = 0.f, s3 = 0.f;
#pragma unroll
        for (int j = 0; j < 2; j++) {
            int i = j * 256 + t;           // uint4-output index, 0..511
            float4 za = zr[2 * i];
            float4 zb = zr[2 * i + 1];
            float4 a2 = u2p[2 * i];
            float4 b2 = u2p[2 * i + 1];
            float4 a3 = u3p[2 * i];
            float4 b3 = u3p[2 * i + 1];
            s2 += za.x * a2.x + za.y * a2.y + za.z * a2.z + za.w * a2.w;
            s2 += zb.x * b2.x + zb.y * b2.y + zb.z * b2.z + zb.w * b2.w;
            s3 += za.x * a3.x + za.y * a3.y + za.z * a3.z + za.w * a3.w;
            s3 += zb.x * b3.x + zb.y * b3.y + zb.z * b3.z + zb.w * b3.w;
            uint4 pv;
            pv.x = pack_h2(za.x, za.y);
            pv.y = pack_h2(za.z, za.w);
            pv.z = pack_h2(zb.x, zb.y);
            pv.w = pack_h2(zb.z, zb.w);
            zo[i] = pv;
        }
#pragma unroll
        for (int o = 16; o > 0; o >>= 1) {
            s2 += __shfl_xor_sync(0xFFFFFFFFu, s2, o);
            s3 += __shfl_xor_sync(0xFFFFFFFFu, s3, o);
        }
        __shared__ float r2[8], r3[8];
        int wid = t >> 5, lid = t & 31;
        if (lid == 0) { r2[wid] = s2; r3[wid] = s3; }
        __syncthreads();
        if (t == 0) {
            float a = 0.f, c = 0.f;
#pragma unroll
            for (int i = 0; i < 8; i++) { a += r2[i]; c += r3[i]; }
            g_c[b] = a * c;
        }
    } else {
        const float4* w4 = (const float4*)W;
        const float4* u4 = (const float4*)U1;
        uint4* wo = (uint4*)g_w;
        size_t total = (size_t)OO * (DD / 8);   // uint4 outputs
        size_t stride = (size_t)2048 * 256;
        for (size_t f = (size_t)(blockIdx.x - BB) * 256 + t; f < total; f += stride) {
            float4 wa = w4[2 * f];
            float4 wb = w4[2 * f + 1];
            size_t ui = (2 * f) & (DD / 4 - 1);
            float4 ua = u4[ui];
            float4 ub = u4[ui + 1];
            uint4 pv;
            pv.x = pack_h2(wa.x * ua.x, wa.y * ua.y);
            pv.y = pack_h2(wa.z * ua.z, wa.w * ua.w);
            pv.z = pack_h2(wb.x * ub.x, wb.y * ub.y);
            pv.w = pack_h2(wb.z * ub.z, wb.w * ub.w);
            wo[f] = pv;
        }
    }
}

// ---------------- GEMM: out[b,o] = c[b]*sum_k z16[b,k]*w16[o,k] + bias[o] ---
// CTA tile 128(M) x 256(N), K-chunk 64, 256 threads (8 warps), warp tile 64x64.
// sm_103 legacy HMMA dispatches at ~16 cyc/SMSP regardless of accumulator;
// floor = #MMA x 16. This round harvests the margins:
//  - promote of prev iter's f16 chain moved into the phase-0 LDSM shadow
//  - first MMA per tile uses zero-C form (no dch zeroing)
#define TM 128
#define TN 256
#define KITERS (DD / 64)                // 64
#define STAGES 3
#define PITCH 144u
#define STG_A (TM * PITCH)              // 18432
#define STG_B (TN * PITCH)              // 36864
#define STG_BYTES (STG_A + STG_B)       // 55296
#define GEMM_SMEM (STAGES * STG_BYTES)  // 165888

__global__ void __launch_bounds__(256, 1) gemm_kernel(const float* __restrict__ bias,
                                                      float* __restrict__ out) {
    extern __shared__ char smem[];
    uint32_t sb = smem_u32(smem);
    int tid = threadIdx.x;
    int wid = tid >> 5, lane = tid & 31;
    int m0 = blockIdx.y * TM;
    int n0 = blockIdx.x * TN;
    int wm = wid & 1;        // 2 M warp-groups of 64
    int wn = wid >> 1;       // 4 N warp-groups of 64

    float acc[4][8][4];
#pragma unroll
    for (int i = 0; i < 4; i++)
#pragma unroll
        for (int j = 0; j < 8; j++)
#pragma unroll
            for (int q = 0; q < 4; q++) acc[i][j][q] = 0.f;

    uint32_t dch[4][8][2];   // f16 chain accumulators (written by zero-C MMA at ks=0)

    const __half* zb = g_z + (size_t)m0 * DD;
    const __half* wb = g_w + (size_t)n0 * DD;

    auto load_stage = [&](int it) {
        int s = it - (it / STAGES) * STAGES;
        uint32_t base = sb + (uint32_t)s * STG_BYTES;
        int kb = it * 64;
#pragma unroll
        for (int j = 0; j < 4; j++) {
            int c = tid + (j << 8);
            int r = c >> 3, ch = c & 7;
            cp_async16(base + (uint32_t)r * PITCH + (uint32_t)(ch << 4),
                       zb + (size_t)r * DD + kb + (ch << 3));
        }
#pragma unroll
        for (int j = 0; j < 8; j++) {
            int c = tid + (j << 8);
            int r = c >> 3, ch = c & 7;
            cp_async16(base + STG_A + (uint32_t)r * PITCH + (uint32_t)(ch << 4),
                       wb + (size_t)r * DD + kb + (ch << 3));
        }
        cp_commit();
    };

#pragma unroll
    for (int p = 0; p < STAGES - 1; p++) load_stage(p);

    // intra-warp ldmatrix offsets
    uint32_t a_row = (uint32_t)(wm * 64 + (lane & 15));
    uint32_t a_kof = (uint32_t)((lane >> 4) << 3) * 2u;
    uint32_t b_row = (uint32_t)(wn * 64 + ((lane >> 4) << 3) + (lane & 7));
    uint32_t b_kof = (uint32_t)(((lane >> 3) & 1) << 3) * 2u;

    for (int it = 0; it < KITERS; ++it) {
        if (it < KITERS - 1) cp_wait<1>();
        else                 cp_wait<0>();
        __syncthreads();

        if (it + STAGES - 1 < KITERS) load_stage(it + STAGES - 1);

        int s = it - (it / STAGES) * STAGES;
        uint32_t aS = sb + (uint32_t)s * STG_BYTES;
        uint32_t bS = aS + STG_A;

        // ---- phase 0: issue fragment loads, then promote prev iter's dch
        uint32_t bf[4][4];
#pragma unroll
        for (int pj = 0; pj < 4; pj++)
            ldsm_x4(bf[pj], bS + (b_row + (uint32_t)(pj * 16)) * PITCH + b_kof);
        uint32_t af0[4];
        ldsm_x4(af0, aS + a_row * PITCH + a_kof);

        if (it) {
            // promote previous iteration's chains while LDSMs are in flight
#pragma unroll
            for (int mi = 0; mi < 4; mi++)
#pragma unroll
                for (int nj = 0; nj < 8; nj++) {
                    float2 f0 = __half22float2(*(__half2*)&dch[mi][nj][0]);
                    float2 f1 = __half22float2(*(__half2*)&dch[mi][nj][1]);
                    acc[mi][nj][0] += f0.x;
                    acc[mi][nj][1] += f0.y;
                    acc[mi][nj][2] += f1.x;
                    acc[mi][nj][3] += f1.y;
                }
        }

        // phase-0 MMAs (zero-C: start fresh chains)
#pragma unroll
        for (int mi = 0; mi < 4; mi++) {
            uint32_t af[4];
            if (mi == 0) {
#pragma unroll
                for (int q = 0; q < 4; q++) af[q] = af0[q];
            } else {
                ldsm_x4(af, aS + (a_row + (uint32_t)(mi * 16)) * PITCH + a_kof);
            }
#pragma unroll
            for (int nj = 0; nj < 8; nj++)
                mma16816_f16_z(dch[mi][nj][0], dch[mi][nj][1],
                               af, &bf[nj >> 1][(nj & 1) * 2]);
        }

        // ---- phases 1..3: chained
#pragma unroll
        for (int ks = 1; ks < 4; ks++) {
            uint32_t koff = (uint32_t)(ks * 32);
#pragma unroll
            for (int pj = 0; pj < 4; pj++)
                ldsm_x4(bf[pj], bS + (b_row + (uint32_t)(pj * 16)) * PITCH + koff + b_kof);
#pragma unroll
            for (int mi = 0; mi < 4; mi++) {
                uint32_t af[4];
                ldsm_x4(af, aS + (a_row + (uint32_t)(mi * 16)) * PITCH + koff + a_kof);
#pragma unroll
                for (int nj = 0; nj < 8; nj++)
                    mma16816_f16(dch[mi][nj][0], dch[mi][nj][1],
                                 af, &bf[nj >> 1][(nj & 1) * 2]);
            }
        }
    }

    // final promote (last iteration's chains)
#pragma unroll
    for (int mi = 0; mi < 4; mi++)
#pragma unroll
        for (int nj = 0; nj < 8; nj++) {
            float2 f0 = __half22float2(*(__half2*)&dch[mi][nj][0]);
            float2 f1 = __half22float2(*(__half2*)&dch[mi][nj][1]);
            acc[mi][nj][0] += f0.x;
            acc[mi][nj][1] += f0.y;
            acc[mi][nj][2] += f1.x;
            acc[mi][nj][3] += f1.y;
        }
    __syncthreads();

    // epilogue: out = c[m]*acc + bias[n]
    int col_base = n0 + wn * 64 + (lane & 3) * 2;
    float bb[8][2];
#pragma unroll
    for (int nj = 0; nj < 8; nj++) {
        bb[nj][0] = __ldg(bias + col_base + nj * 8);
        bb[nj][1] = __ldg(bias + col_base + nj * 8 + 1);
    }
#pragma unroll
    for (int mi = 0; mi < 4; mi++) {
        int r0 = m0 + wm * 64 + mi * 16 + (lane >> 2);
        float c0 = __ldg(g_c + r0);
        float c1 = __ldg(g_c + r0 + 8);
        float* o0 = out + (size_t)r0 * OO;
        float* o1 = o0 + (size_t)8 * OO;
#pragma unroll
        for (int nj = 0; nj < 8; nj++) {
            int col = col_base + nj * 8;
            float2 v0, v1;
            v0.x = c0 * acc[mi][nj][0] + bb[nj][0];
            v0.y = c0 * acc[mi][nj][1] + bb[nj][1];
            v1.x = c1 * acc[mi][nj][2] + bb[nj][0];
            v1.y = c1 * acc[mi][nj][3] + bb[nj][1];
            *(float2*)(o0 + col) = v0;
            *(float2*)(o1 + col) = v1;
        }
    }
}

// ---------------- launch ----------------------------------------------------
extern "C" void kernel_launch(void* const* d_in, const int* in_sizes, int n_in,
                              void* d_out, int out_size) {
    (void)in_sizes; (void)n_in; (void)out_size;
    const float* z    = (const float*)d_in[0];
    const float* U1   = (const float*)d_in[1];
    const float* U2   = (const float*)d_in[2];
    const float* U3   = (const float*)d_in[3];
    const float* W    = (const float*)d_in[4];
    const float* bias = (const float*)d_in[5];
    float* out = (float*)d_out;

    prep_kernel<<<BB + 2048, 256>>>(z, U1, U2, U3, W);

    static bool attr_set = false;
    if (!attr_set) {
        cudaFuncSetAttribute(gemm_kernel, cudaFuncAttributeMaxDynamicSharedMemorySize,
                             GEMM_SMEM);
        attr_set = true;
    }
    dim3 grid(OO / TN, BB / TM);
    gemm_kernel<<<grid, 256, GEMM_SMEM>>>(bias, out);
}